// round 6
// baseline (speedup 1.0000x reference)
#include <cuda_runtime.h>
#include <cuda_fp16.h>
#include <cstdint>
#include <cstddef>

// ---------------- problem constants ----------------
#define OUT_F   11008
#define IN_F    4096
#define TOKENS  4096
#define NGROUPS 32
#define PACKED  (OUT_F * IN_F / 2)

// ---------------- scratch (device globals: allowed) ----------------
__device__ __half W16[(size_t)OUT_F * IN_F];   // dequantized weights, fp16 (~90MB)
__device__ __half X16[(size_t)TOKENS * IN_F];  // activations, fp16 (~33MB)

// ---------------- helpers ----------------
__device__ __forceinline__ uint32_t smem_u32(const void* p) {
    uint32_t a;
    asm("{ .reg .u64 t; cvta.to.shared.u64 t, %1; cvt.u32.u64 %0, t; }" : "=r"(a) : "l"(p));
    return a;
}
__device__ __forceinline__ uint32_t swz(uint32_t o) { return o ^ ((o >> 3) & 0x70u); }

#define CP_ASYNC16(saddr, gptr) \
    asm volatile("cp.async.cg.shared.global [%0], [%1], 16;" :: "r"(saddr), "l"(gptr))
#define CP_COMMIT() asm volatile("cp.async.commit_group;")
#define CP_WAIT(n)  asm volatile("cp.async.wait_group %0;" :: "n"(n))

#define LDSM_X4(r, addr) \
    asm volatile("ldmatrix.sync.aligned.m8n8.x4.shared.b16 {%0,%1,%2,%3}, [%4];" \
                 : "=r"((r)[0]), "=r"((r)[1]), "=r"((r)[2]), "=r"((r)[3]) : "r"(addr))

#define MMA16816(d, a, b0, b1) \
    asm volatile("mma.sync.aligned.m16n8k16.row.col.f32.f16.f16.f32 " \
                 "{%0,%1,%2,%3}, {%4,%5,%6,%7}, {%8,%9}, {%0,%1,%2,%3};" \
                 : "+f"((d)[0]), "+f"((d)[1]), "+f"((d)[2]), "+f"((d)[3]) \
                 : "r"((a)[0]), "r"((a)[1]), "r"((a)[2]), "r"((a)[3]), "r"(b0), "r"(b1))

// ---------------- pre-pass: dequantize W -> fp16 ----------------
__global__ void __launch_bounds__(256) dequant_w_kernel(
    const int* __restrict__ wp, const float* __restrict__ ws, const int* __restrict__ wz) {
    int idx = blockIdx.x * 256 + threadIdx.x;        // 4 packed bytes per thread
    int p4 = idx << 2;
    int o = p4 >> 11;                                // 2048 bytes per out-row
    int p = p4 & 2047;
    int g = p >> 6;                                  // 64 bytes per 128-elem group
    float s = ws[o * NGROUPS + g];
    float z = (float)wz[o * NGROUPS + g];
    int4 b = ((const int4*)wp)[idx];
    int bs[4] = {b.x, b.y, b.z, b.w};
    __half h[8];
#pragma unroll
    for (int j = 0; j < 4; j++) {
        int lo = ((bs[j] & 15) ^ 8) - 8;             // signed int4
        int hi = (((bs[j] >> 4) & 15) ^ 8) - 8;
        h[2 * j]     = __float2half_rn(((float)lo - z) * s);
        h[2 * j + 1] = __float2half_rn(((float)hi - z) * s);
    }
    *(uint4*)(W16 + (size_t)o * IN_F + 2 * p) = *(uint4*)h;
}

// ---------------- pre-pass: x -> fp16 ----------------
__global__ void __launch_bounds__(256) conv_x_kernel(const float* __restrict__ x) {
    size_t idx = (size_t)blockIdx.x * 256 + threadIdx.x;   // 8 floats per thread
    const float4* xp = (const float4*)x + idx * 2;
    float4 a = xp[0], b = xp[1];
    __half h[8];
    h[0] = __float2half_rn(a.x); h[1] = __float2half_rn(a.y);
    h[2] = __float2half_rn(a.z); h[3] = __float2half_rn(a.w);
    h[4] = __float2half_rn(b.x); h[5] = __float2half_rn(b.y);
    h[6] = __float2half_rn(b.z); h[7] = __float2half_rn(b.w);
    *(uint4*)(X16 + idx * 8) = *(uint4*)h;
}

// ---------------- GEMM: 256x128x64 CTA tile, 3-stage cp.async, mma.sync ----------------
static constexpr int TM = 256, TN = 128, TK = 64;
static constexpr int NKIT = IN_F / TK;               // 64
static constexpr int A_BYTES = TM * TK * 2;          // 32KB
static constexpr int B_BYTES = TN * TK * 2;          // 16KB
static constexpr int STAGE_B = A_BYTES + B_BYTES;    // 48KB
static constexpr int STAGES = 3;
static constexpr int SMEM_BYTES = STAGES * STAGE_B + 1024;   // ~145KB

__global__ void __launch_bounds__(512, 1) gemm_kernel(float* __restrict__ out) {
    extern __shared__ char smem_raw[];
    uint32_t sraw = smem_u32(smem_raw);
    uint32_t sbase = (sraw + 1023) & ~1023u;         // 1KB align for clean swizzle
    int tid = threadIdx.x;
    int lane = tid & 31, wid = tid >> 5;
    int warp_m = wid & 3, warp_n = wid >> 2;         // 4 x 4 warp grid
    int m0 = blockIdx.y * TM;
    int n0 = blockIdx.x * TN;

    // cp.async fill of one pipeline stage
    auto fill = [&](int st, int kt) {
        int k0 = kt * TK;
        uint32_t abase = sbase + st * STAGE_B;
#pragma unroll
        for (int i = 0; i < 4; i++) {                // A: 2048 x 16B chunks
            int c = tid + 512 * i;
            int row = c >> 3, c8 = c & 7;
            const __half* g = X16 + (size_t)(m0 + row) * IN_F + k0 + c8 * 8;
            CP_ASYNC16(abase + swz((uint32_t)(row * 128 + c8 * 16)), g);
        }
#pragma unroll
        for (int i = 0; i < 2; i++) {                // B: 1024 x 16B chunks
            int c = tid + 512 * i;
            int row = c >> 3, c8 = c & 7;
            const __half* g = W16 + (size_t)(n0 + row) * IN_F + k0 + c8 * 8;
            CP_ASYNC16(abase + A_BYTES + swz((uint32_t)(row * 128 + c8 * 16)), g);
        }
    };

    // lane-derived ldmatrix row/col offsets
    int lmA_r = (lane & 7) + ((lane >> 3) & 1) * 8;  // m within 16
    int lmA_k = (lane >> 4) * 8;                     // 0 | 8
    int lmB_r = (lane & 7) + (lane >> 4) * 8;        // n within 16
    int lmB_k = ((lane >> 3) & 1) * 8;               // 0 | 8

    float acc[4][4][4];
#pragma unroll
    for (int i = 0; i < 4; i++)
#pragma unroll
        for (int j = 0; j < 4; j++)
#pragma unroll
            for (int k = 0; k < 4; k++) acc[i][j][k] = 0.0f;

    fill(0, 0); CP_COMMIT();
    fill(1, 1); CP_COMMIT();

    int st = 0;
#pragma unroll 1
    for (int kt = 0; kt < NKIT; kt++) {
        CP_WAIT(1);                                  // stage kt's data resident
        __syncthreads();                             // also proves stage kt+2 slot free
        if (kt + 2 < NKIT) fill((st + 2 >= STAGES) ? st + 2 - STAGES : st + 2, kt + 2);
        CP_COMMIT();                                 // empty group at tail keeps ladder sane

        uint32_t Ab = sbase + st * STAGE_B;
        uint32_t Bb = Ab + A_BYTES;
#pragma unroll
        for (int kk = 0; kk < 4; kk++) {             // 4 x k16 steps
            uint32_t ra[4][4];
#pragma unroll
            for (int tm = 0; tm < 4; tm++) {
                uint32_t addr = Ab + swz((uint32_t)((warp_m * 64 + tm * 16 + lmA_r) * 128 +
                                                    (kk * 16 + lmA_k) * 2));
                LDSM_X4(ra[tm], addr);
            }
            // B tile [n][k] == col-major B for mma -> NON-trans ldmatrix
            uint32_t rb[2][4];
#pragma unroll
            for (int tg = 0; tg < 2; tg++) {
                uint32_t addr = Bb + swz((uint32_t)((warp_n * 32 + tg * 16 + lmB_r) * 128 +
                                                    (kk * 16 + lmB_k) * 2));
                LDSM_X4(rb[tg], addr);
            }
#pragma unroll
            for (int tm = 0; tm < 4; tm++) {
#pragma unroll
                for (int tn = 0; tn < 4; tn++) {
                    uint32_t b0 = rb[tn >> 1][(tn & 1) * 2];
                    uint32_t b1 = rb[tn >> 1][(tn & 1) * 2 + 1];
                    MMA16816(acc[tm][tn], ra[tm], b0, b1);
                }
            }
        }
        st = (st + 1 == STAGES) ? 0 : st + 1;
    }

    // epilogue: direct register -> gmem (float2 stores)
#pragma unroll
    for (int tm = 0; tm < 4; tm++) {
#pragma unroll
        for (int tn = 0; tn < 4; tn++) {
            int row = m0 + warp_m * 64 + tm * 16 + (lane >> 2);
            int col = n0 + warp_n * 32 + tn * 8 + (lane & 3) * 2;
            float2 v0 = make_float2(acc[tm][tn][0], acc[tm][tn][1]);
            float2 v1 = make_float2(acc[tm][tn][2], acc[tm][tn][3]);
            *(float2*)(out + (size_t)row * OUT_F + col) = v0;
            *(float2*)(out + (size_t)(row + 8) * OUT_F + col) = v1;
        }
    }
}

// ---------------- launch ----------------
extern "C" void kernel_launch(void* const* d_in, const int* in_sizes, int n_in,
                              void* d_out, int out_size) {
    (void)in_sizes; (void)n_in; (void)out_size;
    const float* x  = (const float*)d_in[0];
    const int*   wp = (const int*)d_in[1];
    const float* ws = (const float*)d_in[2];
    const int*   wz = (const int*)d_in[3];
    float* out = (float*)d_out;

    cudaFuncSetAttribute(gemm_kernel, cudaFuncAttributeMaxDynamicSharedMemorySize, SMEM_BYTES);

    dequant_w_kernel<<<PACKED / 4 / 256, 256>>>(wp, ws, wz);
    conv_x_kernel<<<(size_t)TOKENS * IN_F / 8 / 256, 256>>>(x);
    gemm_kernel<<<dim3(OUT_F / TN, TOKENS / TM), 512, SMEM_BYTES>>>(out);
}

// round 7
// speedup vs baseline: 1.1173x; 1.1173x over previous
#include <cuda_runtime.h>
#include <cuda_fp16.h>
#include <cstdint>
#include <cstddef>

// ---------------- problem constants ----------------
#define OUT_F   11008
#define IN_F    4096
#define TOKENS  4096
#define NGROUPS 32
#define PACKED  (OUT_F * IN_F / 2)

// ---------------- scratch (device globals: allowed) ----------------
__device__ __half W16[(size_t)OUT_F * IN_F];   // dequantized weights, fp16 (~90MB)
__device__ __half X16[(size_t)TOKENS * IN_F];  // activations, fp16 (~33MB)

// ---------------- helpers ----------------
__device__ __forceinline__ uint32_t smem_u32(const void* p) {
    uint32_t a;
    asm("{ .reg .u64 t; cvta.to.shared.u64 t, %1; cvt.u32.u64 %0, t; }" : "=r"(a) : "l"(p));
    return a;
}
__device__ __forceinline__ uint32_t swz(uint32_t o) { return o ^ ((o >> 3) & 0x70u); }

#define CP_ASYNC16(saddr, gptr) \
    asm volatile("cp.async.cg.shared.global [%0], [%1], 16;" :: "r"(saddr), "l"(gptr))
#define CP_COMMIT() asm volatile("cp.async.commit_group;")
#define CP_WAIT(n)  asm volatile("cp.async.wait_group %0;" :: "n"(n))

#define LDSM_X4(r, addr) \
    asm volatile("ldmatrix.sync.aligned.m8n8.x4.shared.b16 {%0,%1,%2,%3}, [%4];" \
                 : "=r"((r)[0]), "=r"((r)[1]), "=r"((r)[2]), "=r"((r)[3]) : "r"(addr))

#define MMA16816(d, a, b0, b1) \
    asm volatile("mma.sync.aligned.m16n8k16.row.col.f32.f16.f16.f32 " \
                 "{%0,%1,%2,%3}, {%4,%5,%6,%7}, {%8,%9}, {%0,%1,%2,%3};" \
                 : "+f"((d)[0]), "+f"((d)[1]), "+f"((d)[2]), "+f"((d)[3]) \
                 : "r"((a)[0]), "r"((a)[1]), "r"((a)[2]), "r"((a)[3]), "r"(b0), "r"(b1))

// ---------------- pre-pass: dequantize W -> fp16 ----------------
__global__ void __launch_bounds__(256) dequant_w_kernel(
    const int* __restrict__ wp, const float* __restrict__ ws, const int* __restrict__ wz) {
    int idx = blockIdx.x * 256 + threadIdx.x;        // 4 packed bytes per thread
    int p4 = idx << 2;
    int o = p4 >> 11;                                // 2048 bytes per out-row
    int p = p4 & 2047;
    int g = p >> 6;                                  // 64 bytes per 128-elem group
    float s = ws[o * NGROUPS + g];
    float z = (float)wz[o * NGROUPS + g];
    int4 b = ((const int4*)wp)[idx];
    int bs[4] = {b.x, b.y, b.z, b.w};
    __half h[8];
#pragma unroll
    for (int j = 0; j < 4; j++) {
        int lo = ((bs[j] & 15) ^ 8) - 8;             // signed int4
        int hi = (((bs[j] >> 4) & 15) ^ 8) - 8;
        h[2 * j]     = __float2half_rn(((float)lo - z) * s);
        h[2 * j + 1] = __float2half_rn(((float)hi - z) * s);
    }
    *(uint4*)(W16 + (size_t)o * IN_F + 2 * p) = *(uint4*)h;
}

// ---------------- pre-pass: x -> fp16 ----------------
__global__ void __launch_bounds__(256) conv_x_kernel(const float* __restrict__ x) {
    size_t idx = (size_t)blockIdx.x * 256 + threadIdx.x;   // 8 floats per thread
    const float4* xp = (const float4*)x + idx * 2;
    float4 a = xp[0], b = xp[1];
    __half h[8];
    h[0] = __float2half_rn(a.x); h[1] = __float2half_rn(a.y);
    h[2] = __float2half_rn(a.z); h[3] = __float2half_rn(a.w);
    h[4] = __float2half_rn(b.x); h[5] = __float2half_rn(b.y);
    h[6] = __float2half_rn(b.z); h[7] = __float2half_rn(b.w);
    *(uint4*)(X16 + idx * 8) = *(uint4*)h;
}

// ---------------- GEMM: 128x128x64 CTA tile, 3-stage cp.async, occ=2 ----------------
static constexpr int TM = 128, TN = 128, TK = 64;
static constexpr int NKIT = IN_F / TK;               // 64
static constexpr int A_BYTES = TM * TK * 2;          // 16KB
static constexpr int B_BYTES = TN * TK * 2;          // 16KB
static constexpr int STAGE_B = A_BYTES + B_BYTES;    // 32KB
static constexpr int STAGES = 3;
static constexpr int SMEM_BYTES = STAGES * STAGE_B + 1024;   // ~97KB (2 CTAs fit in 228KB)

__global__ void __launch_bounds__(256, 2) gemm_kernel(float* __restrict__ out) {
    extern __shared__ char smem_raw[];
    uint32_t sraw = smem_u32(smem_raw);
    uint32_t sbase = (sraw + 1023) & ~1023u;         // 1KB align for clean swizzle
    int tid = threadIdx.x;
    int lane = tid & 31, wid = tid >> 5;
    int warp_m = wid & 1, warp_n = wid >> 1;         // 2 x 4 warp grid
    int m0 = blockIdx.y * TM;
    int n0 = blockIdx.x * TN;

    // cp.async fill of one pipeline stage
    auto fill = [&](int st, int kt) {
        int k0 = kt * TK;
        uint32_t abase = sbase + st * STAGE_B;
#pragma unroll
        for (int i = 0; i < 4; i++) {                // A: 1024 x 16B chunks
            int c = tid + 256 * i;
            int row = c >> 3, c8 = c & 7;
            const __half* g = X16 + (size_t)(m0 + row) * IN_F + k0 + c8 * 8;
            CP_ASYNC16(abase + swz((uint32_t)(row * 128 + c8 * 16)), g);
        }
#pragma unroll
        for (int i = 0; i < 4; i++) {                // B: 1024 x 16B chunks
            int c = tid + 256 * i;
            int row = c >> 3, c8 = c & 7;
            const __half* g = W16 + (size_t)(n0 + row) * IN_F + k0 + c8 * 8;
            CP_ASYNC16(abase + A_BYTES + swz((uint32_t)(row * 128 + c8 * 16)), g);
        }
    };

    // lane-derived ldmatrix row/col offsets
    int lmA_r = (lane & 7) + ((lane >> 3) & 1) * 8;  // m within 16
    int lmA_k = (lane >> 4) * 8;                     // 0 | 8
    int lmB_r = (lane & 7) + (lane >> 4) * 8;        // n within 16
    int lmB_k = ((lane >> 3) & 1) * 8;               // 0 | 8

    float acc[4][4][4];
#pragma unroll
    for (int i = 0; i < 4; i++)
#pragma unroll
        for (int j = 0; j < 4; j++)
#pragma unroll
            for (int k = 0; k < 4; k++) acc[i][j][k] = 0.0f;

    fill(0, 0); CP_COMMIT();
    fill(1, 1); CP_COMMIT();

    int st = 0;
#pragma unroll 1
    for (int kt = 0; kt < NKIT; kt++) {
        CP_WAIT(1);                                  // stage kt's data resident
        __syncthreads();                             // readers of stage kt-1 are done too
        if (kt + 2 < NKIT) fill((st + 2 >= STAGES) ? st + 2 - STAGES : st + 2, kt + 2);
        CP_COMMIT();                                 // empty group at tail keeps ladder sane

        uint32_t Ab = sbase + st * STAGE_B;
        uint32_t Bb = Ab + A_BYTES;
#pragma unroll
        for (int kk = 0; kk < 4; kk++) {             // 4 x k16 steps
            uint32_t ra[4][4];
#pragma unroll
            for (int tm = 0; tm < 4; tm++) {
                uint32_t addr = Ab + swz((uint32_t)((warp_m * 64 + tm * 16 + lmA_r) * 128 +
                                                    (kk * 16 + lmA_k) * 2));
                LDSM_X4(ra[tm], addr);
            }
            // B tile [n][k] == col-major B for mma -> NON-trans ldmatrix
            uint32_t rb[2][4];
#pragma unroll
            for (int tg = 0; tg < 2; tg++) {
                uint32_t addr = Bb + swz((uint32_t)((warp_n * 32 + tg * 16 + lmB_r) * 128 +
                                                    (kk * 16 + lmB_k) * 2));
                LDSM_X4(rb[tg], addr);
            }
#pragma unroll
            for (int tm = 0; tm < 4; tm++) {
#pragma unroll
                for (int tn = 0; tn < 4; tn++) {
                    uint32_t b0 = rb[tn >> 1][(tn & 1) * 2];
                    uint32_t b1 = rb[tn >> 1][(tn & 1) * 2 + 1];
                    MMA16816(acc[tm][tn], ra[tm], b0, b1);
                }
            }
        }
        st = (st + 1 == STAGES) ? 0 : st + 1;
    }

    // epilogue: direct register -> gmem (float2 stores)
#pragma unroll
    for (int tm = 0; tm < 4; tm++) {
#pragma unroll
        for (int tn = 0; tn < 4; tn++) {
            int row = m0 + warp_m * 64 + tm * 16 + (lane >> 2);
            int col = n0 + warp_n * 32 + tn * 8 + (lane & 3) * 2;
            float2 v0 = make_float2(acc[tm][tn][0], acc[tm][tn][1]);
            float2 v1 = make_float2(acc[tm][tn][2], acc[tm][tn][3]);
            *(float2*)(out + (size_t)row * OUT_F + col) = v0;
            *(float2*)(out + (size_t)(row + 8) * OUT_F + col) = v1;
        }
    }
}

// ---------------- launch ----------------
extern "C" void kernel_launch(void* const* d_in, const int* in_sizes, int n_in,
                              void* d_out, int out_size) {
    (void)in_sizes; (void)n_in; (void)out_size;
    const float* x  = (const float*)d_in[0];
    const int*   wp = (const int*)d_in[1];
    const float* ws = (const float*)d_in[2];
    const int*   wz = (const int*)d_in[3];
    float* out = (float*)d_out;

    cudaFuncSetAttribute(gemm_kernel, cudaFuncAttributeMaxDynamicSharedMemorySize, SMEM_BYTES);

    dequant_w_kernel<<<PACKED / 4 / 256, 256>>>(wp, ws, wz);
    conv_x_kernel<<<(size_t)TOKENS * IN_F / 8 / 256, 256>>>(x);
    gemm_kernel<<<dim3(OUT_F / TN, TOKENS / TM), 256, SMEM_BYTES>>>(out);
}

// round 10
// speedup vs baseline: 1.1370x; 1.0176x over previous
#include <cuda_runtime.h>
#include <cuda_fp16.h>
#include <cstdint>
#include <cstddef>

// ---------------- problem constants ----------------
#define OUT_F   11008
#define IN_F    4096
#define TOKENS  4096
#define NGROUPS 32
#define PACKED  (OUT_F * IN_F / 2)

// ---------------- scratch (device globals: allowed) ----------------
__device__ __half W16[(size_t)OUT_F * IN_F];   // dequantized weights, fp16 (~90MB)
__device__ __half X16[(size_t)TOKENS * IN_F];  // activations, fp16 (~33MB)

// ---------------- helpers ----------------
__device__ __forceinline__ uint32_t smem_u32(const void* p) {
    uint32_t a;
    asm("{ .reg .u64 t; cvta.to.shared.u64 t, %1; cvt.u32.u64 %0, t; }" : "=r"(a) : "l"(p));
    return a;
}
__device__ __forceinline__ uint32_t swz(uint32_t o) { return o ^ ((o >> 3) & 0x70u); }

#define CP_ASYNC16(saddr, gptr) \
    asm volatile("cp.async.cg.shared.global [%0], [%1], 16;" :: "r"(saddr), "l"(gptr))
#define CP_COMMIT() asm volatile("cp.async.commit_group;")
#define CP_WAIT(n)  asm volatile("cp.async.wait_group %0;" :: "n"(n))

#define LDSM_X4(r, addr) \
    asm volatile("ldmatrix.sync.aligned.m8n8.x4.shared.b16 {%0,%1,%2,%3}, [%4];" \
                 : "=r"((r)[0]), "=r"((r)[1]), "=r"((r)[2]), "=r"((r)[3]) : "r"(addr))

#define MMA16816(d, a, b0, b1) \
    asm volatile("mma.sync.aligned.m16n8k16.row.col.f32.f16.f16.f32 " \
                 "{%0,%1,%2,%3}, {%4,%5,%6,%7}, {%8,%9}, {%0,%1,%2,%3};" \
                 : "+f"((d)[0]), "+f"((d)[1]), "+f"((d)[2]), "+f"((d)[3]) \
                 : "r"((a)[0]), "r"((a)[1]), "r"((a)[2]), "r"((a)[3]), "r"(b0), "r"(b1))

// ---------------- pre-pass: dequantize W -> fp16 ----------------
__global__ void __launch_bounds__(256) dequant_w_kernel(
    const int* __restrict__ wp, const float* __restrict__ ws, const int* __restrict__ wz) {
    int idx = blockIdx.x * 256 + threadIdx.x;        // 4 packed bytes per thread
    int p4 = idx << 2;
    int o = p4 >> 11;                                // 2048 bytes per out-row
    int p = p4 & 2047;
    int g = p >> 6;                                  // 64 bytes per 128-elem group
    float s = ws[o * NGROUPS + g];
    float z = (float)wz[o * NGROUPS + g];
    int4 b = ((const int4*)wp)[idx];
    int bs[4] = {b.x, b.y, b.z, b.w};
    __half h[8];
#pragma unroll
    for (int j = 0; j < 4; j++) {
        int lo = ((bs[j] & 15) ^ 8) - 8;             // signed int4
        int hi = (((bs[j] >> 4) & 15) ^ 8) - 8;
        h[2 * j]     = __float2half_rn(((float)lo - z) * s);
        h[2 * j + 1] = __float2half_rn(((float)hi - z) * s);
    }
    *(uint4*)(W16 + (size_t)o * IN_F + 2 * p) = *(uint4*)h;
}

// ---------------- pre-pass: x -> fp16 ----------------
__global__ void __launch_bounds__(256) conv_x_kernel(const float* __restrict__ x) {
    size_t idx = (size_t)blockIdx.x * 256 + threadIdx.x;   // 8 floats per thread
    const float4* xp = (const float4*)x + idx * 2;
    float4 a = xp[0], b = xp[1];
    __half h[8];
    h[0] = __float2half_rn(a.x); h[1] = __float2half_rn(a.y);
    h[2] = __float2half_rn(a.z); h[3] = __float2half_rn(a.w);
    h[4] = __float2half_rn(b.x); h[5] = __float2half_rn(b.y);
    h[6] = __float2half_rn(b.z); h[7] = __float2half_rn(b.w);
    *(uint4*)(X16 + idx * 8) = *(uint4*)h;
}

// ---------------- GEMM: 128x128x64 CTA tile, 3-stage cp.async, occ=2 ----------------
static constexpr int TM = 128, TN = 128, TK = 64;
static constexpr int NKIT = IN_F / TK;               // 64
static constexpr int A_BYTES = TM * TK * 2;          // 16KB
static constexpr int B_BYTES = TN * TK * 2;          // 16KB
static constexpr int STAGE_B = A_BYTES + B_BYTES;    // 32KB
static constexpr int STAGES = 3;
static constexpr int SMEM_BYTES = STAGES * STAGE_B + 1024;   // ~97KB (2 CTAs fit in 228KB)
static constexpr int N_TILES = OUT_F / TN;           // 86
static constexpr int M_TILES = TOKENS / TM;          // 32
static constexpr int GROUP_M = 8;                    // raster swizzle group (32 % 8 == 0)

__global__ void __launch_bounds__(256, 2) gemm_kernel(float* __restrict__ out) {
    extern __shared__ char smem_raw[];
    uint32_t sraw = smem_u32(smem_raw);
    uint32_t sbase = (sraw + 1023) & ~1023u;         // 1KB align for clean swizzle
    int tid = threadIdx.x;
    int lane = tid & 31, wid = tid >> 5;
    int warp_m = wid & 1, warp_n = wid >> 1;         // 2 x 4 warp grid

    // GROUP_M rasterization swizzle: wave footprint ~8 m-tiles x 37 n-tiles
    int lin = blockIdx.y * N_TILES + blockIdx.x;
    int group = lin / (GROUP_M * N_TILES);
    int inner = lin % (GROUP_M * N_TILES);
    int pid_m = group * GROUP_M + (inner % GROUP_M);
    int pid_n = inner / GROUP_M;
    int m0 = pid_m * TM;
    int n0 = pid_n * TN;

    // hoisted per-thread fill addressing: thread covers rows r0+32i, fixed 16B column c8
    int r0 = tid >> 3, c8 = tid & 7;
    const __half* gA0 = X16 + (size_t)(m0 + r0) * IN_F + c8 * 8;
    const __half* gB0 = W16 + (size_t)(n0 + r0) * IN_F + c8 * 8;
    uint32_t sOff[4];
#pragma unroll
    for (int i = 0; i < 4; i++)
        sOff[i] = swz((uint32_t)((r0 + 32 * i) * 128 + c8 * 16));

    auto fill = [&](int st, int kt) {
        const __half* ga = gA0 + kt * TK;
        const __half* gb = gB0 + kt * TK;
        uint32_t abase = sbase + st * STAGE_B;
#pragma unroll
        for (int i = 0; i < 4; i++)
            CP_ASYNC16(abase + sOff[i], ga + (size_t)(32 * i) * IN_F);
#pragma unroll
        for (int i = 0; i < 4; i++)
            CP_ASYNC16(abase + A_BYTES + sOff[i], gb + (size_t)(32 * i) * IN_F);
    };

    // lane-derived ldmatrix row/col offsets
    int lmA_r = (lane & 7) + ((lane >> 3) & 1) * 8;  // m within 16
    int lmA_k = (lane >> 4) * 8;                     // 0 | 8
    int lmB_r = (lane & 7) + (lane >> 4) * 8;        // n within 16
    int lmB_k = ((lane >> 3) & 1) * 8;               // 0 | 8

    float acc[4][4][4];
#pragma unroll
    for (int i = 0; i < 4; i++)
#pragma unroll
        for (int j = 0; j < 4; j++)
#pragma unroll
            for (int k = 0; k < 4; k++) acc[i][j][k] = 0.0f;

    fill(0, 0); CP_COMMIT();
    fill(1, 1); CP_COMMIT();

#pragma unroll 3
    for (int kt = 0; kt < NKIT; kt++) {
        int st = kt % STAGES;                        // static under unroll 3
        CP_WAIT(1);                                  // stage kt's data resident
        __syncthreads();                             // readers of stage kt-1 are done too
        if (kt + 2 < NKIT) fill((kt + 2) % STAGES, kt + 2);
        CP_COMMIT();                                 // empty group at tail keeps ladder sane

        uint32_t Ab = sbase + st * STAGE_B;
        uint32_t Bb = Ab + A_BYTES;
#pragma unroll
        for (int kk = 0; kk < 4; kk++) {             // 4 x k16 steps
            uint32_t ra[4][4];
#pragma unroll
            for (int tm = 0; tm < 4; tm++) {
                uint32_t addr = Ab + swz((uint32_t)((warp_m * 64 + tm * 16 + lmA_r) * 128 +
                                                    (kk * 16 + lmA_k) * 2));
                LDSM_X4(ra[tm], addr);
            }
            // B tile [n][k] == col-major B for mma -> NON-trans ldmatrix
            uint32_t rb[2][4];
#pragma unroll
            for (int tg = 0; tg < 2; tg++) {
                uint32_t addr = Bb + swz((uint32_t)((warp_n * 32 + tg * 16 + lmB_r) * 128 +
                                                    (kk * 16 + lmB_k) * 2));
                LDSM_X4(rb[tg], addr);
            }
#pragma unroll
            for (int tm = 0; tm < 4; tm++) {
#pragma unroll
                for (int tn = 0; tn < 4; tn++) {
                    uint32_t b0 = rb[tn >> 1][(tn & 1) * 2];
                    uint32_t b1 = rb[tn >> 1][(tn & 1) * 2 + 1];
                    MMA16816(acc[tm][tn], ra[tm], b0, b1);
                }
            }
        }
    }

    // epilogue: direct register -> gmem (float2 stores)
#pragma unroll
    for (int tm = 0; tm < 4; tm++) {
#pragma unroll
        for (int tn = 0; tn < 4; tn++) {
            int row = m0 + warp_m * 64 + tm * 16 + (lane >> 2);
            int col = n0 + warp_n * 32 + tn * 8 + (lane & 3) * 2;
            float2 v0 = make_float2(acc[tm][tn][0], acc[tm][tn][1]);
            float2 v1 = make_float2(acc[tm][tn][2], acc[tm][tn][3]);
            *(float2*)(out + (size_t)row * OUT_F + col) = v0;
            *(float2*)(out + (size_t)(row + 8) * OUT_F + col) = v1;
        }
    }
}

// ---------------- launch ----------------
extern "C" void kernel_launch(void* const* d_in, const int* in_sizes, int n_in,
                              void* d_out, int out_size) {
    (void)in_sizes; (void)n_in; (void)out_size;
    const float* x  = (const float*)d_in[0];
    const int*   wp = (const int*)d_in[1];
    const float* ws = (const float*)d_in[2];
    const int*   wz = (const int*)d_in[3];
    float* out = (float*)d_out;

    cudaFuncSetAttribute(gemm_kernel, cudaFuncAttributeMaxDynamicSharedMemorySize, SMEM_BYTES);

    dequant_w_kernel<<<PACKED / 4 / 256, 256>>>(wp, ws, wz);
    conv_x_kernel<<<(size_t)TOKENS * IN_F / 8 / 256, 256>>>(x);
    gemm_kernel<<<dim3(N_TILES, M_TILES), 256, SMEM_BYTES>>>(out);
}